// round 17
// baseline (speedup 1.0000x reference)
#include <cuda_runtime.h>
#include <cuda_fp16.h>
#include <cstdint>
#include <math.h>
#include <mma.h>

using namespace nvcuda;

// ---------------- problem constants ----------------
#define DIMC   192
#define HW     56
#define WSZ    7
#define SHIFT  3
#define NHEADS 6
#define HD     32
#define HIDDEN 768
#define BATCH  32
#define NTOK   (HW*HW)          // 3136
#define NBLKS  (BATCH*64)       // 2048 windows
#define NTOKW  49

// ---------------- scratch ----------------
__device__ float g_xattn[(size_t)BATCH * NTOK * DIMC];

// fp16 weight copies (filled once per launch)
#define NW1   (DIMC*HIDDEN)
#define NW2   (HIDDEN*DIMC)
#define NQKV  (DIMC*3*DIMC)
#define NPROJ (DIMC*DIMC)
__device__ __align__(16) __half g_w1h[NW1];
__device__ __align__(16) __half g_w2h[NW2];
__device__ __align__(16) __half g_qkvh[NQKV];
__device__ __align__(16) __half g_projh[NPROJ];

// ---------------- helpers ----------------
__device__ __forceinline__ float warp_sum(float v){
#pragma unroll
    for (int o = 16; o; o >>= 1) v += __shfl_xor_sync(0xffffffffu, v, o);
    return v;
}
__device__ __forceinline__ float warp_max(float v){
#pragma unroll
    for (int o = 16; o; o >>= 1) v = fmaxf(v, __shfl_xor_sync(0xffffffffu, v, o));
    return v;
}
__device__ __forceinline__ float gelu_exact(float x){
    return 0.5f * x * (1.0f + erff(x * 0.70710678118654752440f));
}

// cp.async helpers
__device__ __forceinline__ void cp_async16(void* smem, const void* gmem){
    unsigned int s = (unsigned int)__cvta_generic_to_shared(smem);
    asm volatile("cp.async.cg.shared.global [%0], [%1], 16;\n" :: "r"(s), "l"(gmem));
}
__device__ __forceinline__ void cp_commit(){
    asm volatile("cp.async.commit_group;\n");
}
template<int N>
__device__ __forceinline__ void cp_wait(){
    asm volatile("cp.async.wait_group %0;\n" :: "n"(N));
}

typedef wmma::fragment<wmma::matrix_a, 16, 16, 16, __half, wmma::row_major> FA;
typedef wmma::fragment<wmma::matrix_b, 16, 16, 16, __half, wmma::row_major> FB;
typedef wmma::fragment<wmma::matrix_b, 16, 16, 16, __half, wmma::col_major> FBt;
typedef wmma::fragment<wmma::accumulator, 16, 16, 16, float> FC;

// =====================================================================
// Kernel 0: convert all weights to fp16 once.
// =====================================================================
#define RW_THREADS 256
#define RW_BLOCKS  432   // 110592 4-elem groups / 256

__global__ __launch_bounds__(RW_THREADS)
void prep_kernel(const float* __restrict__ w1, const float* __restrict__ w2,
                 const float* __restrict__ qkv_w, const float* __restrict__ proj_w)
{
    int i = blockIdx.x * RW_THREADS + threadIdx.x;   // 4-elem group index
    const float* src; __half* dst;
    if (i < NW1/4){ src = w1; dst = g_w1h; }
    else if ((i -= NW1/4) < NW2/4){ src = w2; dst = g_w2h; }
    else if ((i -= NW2/4) < NQKV/4){ src = qkv_w; dst = g_qkvh; }
    else if ((i -= NQKV/4) < NPROJ/4){ src = proj_w; dst = g_projh; }
    else return;
    float4 v = ((const float4*)src)[i];
    __half2* d = (__half2*)dst;
    d[2*i  ] = __floats2half2_rn(v.x, v.y);
    d[2*i+1] = __floats2half2_rn(v.z, v.w);
}

// =====================================================================
// Kernel 1: shifted-window attention, fp16 wmma, one CTA per window,
// 384 threads, 2x2 warp tiles, 64-row weight staging (12 chunks).
// Warp-local bias/cvt epilogues (no full-CTA cvt passes).
// =====================================================================
#define AT_THREADS 384
#define FLD  196     // float scratch stride
#define AHL  200     // half stride (192-wide buffers)
#define SHL  72      // half stride (scores)

#define OFF_FS 0                     // float [64][196] = 12544 floats
#define OFF_XH 12544                 // half  [64][200] = 6400 floats
#define OFF_QH (OFF_XH + 6400)
#define OFF_KH (OFF_QH + 6400)
#define OFF_VH (OFF_KH + 6400)
#define OFF_SH (OFF_VH + 6400)       // half [3][64][72] = 6912 floats
#define OFF_BH (OFF_SH + 6912)       // half [64][200]   = 6400 floats
#define ATT_SMEM_FLOATS (OFF_BH + 6400)      // 51456
#define ATT_SMEM_BYTES  (ATT_SMEM_FLOATS*4)  // 205824

__global__ __launch_bounds__(AT_THREADS)
void attn_kernel(const float* __restrict__ x,
                 const float* __restrict__ qkv_b,
                 const float* __restrict__ proj_b,
                 const float* __restrict__ g1, const float* __restrict__ be1)
{
    extern __shared__ float sm[];
    float*  FS = sm + OFF_FS;
    __half* xh = (__half*)(sm + OFF_XH);   // LN'd input; later O (half)
    __half* qh = (__half*)(sm + OFF_QH);
    __half* kh = (__half*)(sm + OFF_KH);
    __half* vh = (__half*)(sm + OFF_VH);
    __half* Sh = (__half*)(sm + OFF_SH);
    __half* bh = (__half*)(sm + OFF_BH);   // weight staging [64][200]

    const int t   = threadIdx.x;
    const int wid = t >> 5, lane = t & 31;
    const int blk = blockIdx.x;
    const int b   = blk >> 6;
    const int win = blk & 63;
    const int wr  = win >> 3, wc = win & 7;

    const float* xb = x + (size_t)b * NTOK * DIMC;

    // staging coords: 64 rows x 192 halfs = 1536 uint4 / 384 threads = 4 each
    int prow[4], pc8[4];
#pragma unroll
    for (int i = 0; i < 4; i++){
        int idx = t + i*AT_THREADS;
        prow[i] = idx / 24; pc8[i] = idx - prow[i]*24;
    }
    uint4 pf[4];
#pragma unroll
    for (int i = 0; i < 4; i++)   // chunk 0: qkv m=0, stage 0
        pf[i] = *(const uint4*)(g_qkvh + (size_t)prow[i]*(3*DIMC) + pc8[i]*8);

    // zero half buffers xh..Sh: floats [OFF_XH, OFF_BH) = 32512 = 8128 float4
    {
        float4 zf = make_float4(0.f,0.f,0.f,0.f);
        float4* zp = (float4*)(sm + OFF_XH);
        for (int idx = t; idx < 8128; idx += AT_THREADS) zp[idx] = zf;
    }

    // gather with cyclic shift (roll -3,-3) into FS
    for (int idx = t; idx < NTOKW*48; idx += AT_THREADS){
        int row = idx / 48, c4 = idx - row*48;
        int ti = row / WSZ, tj = row - ti*WSZ;
        int sr = wr*WSZ + ti + SHIFT; if (sr >= HW) sr -= HW;
        int sc = wc*WSZ + tj + SHIFT; if (sc >= HW) sc -= HW;
        *(float4*)(FS + row*FLD + c4*4) =
            *(const float4*)(xb + (size_t)(sr*HW + sc)*DIMC + c4*4);
    }
    __syncthreads();

    // LN1: read FS, write half xh (rows < 49; pad rows stay 0)
    for (int r = wid; r < NTOKW; r += 12){
        float s = 0.f, s2 = 0.f;
#pragma unroll
        for (int c = lane; c < DIMC; c += 32){
            float v = FS[r*FLD + c]; s += v; s2 += v*v;
        }
        s = warp_sum(s); s2 = warp_sum(s2);
        float mu = s * (1.0f/DIMC);
        float rs = rsqrtf(s2*(1.0f/DIMC) - mu*mu + 1e-5f);
#pragma unroll
        for (int c = lane; c < DIMC; c += 32){
            float v = (FS[r*FLD + c] - mu)*rs*g1[c] + be1[c];
            xh[r*AHL + c] = __float2half_rn(v);
        }
    }

    // 2x2 warp tiling for [64,192] GEMMs (12 warps, 48 tiles)
    const int rt0 = (wid / 6) * 2;
    const int cgi = wid % 6;

    int ci = 0;   // weight chunk stream: 9 qkv + 3 proj (64 k-rows each)

    // ---- QKV ----
    for (int m = 0; m < 3; m++){
        FC acc[2][2];
#pragma unroll
        for (int i = 0; i < 2; i++)
#pragma unroll
            for (int j = 0; j < 2; j++) wmma::fill_fragment(acc[i][j], 0.f);

        for (int kc = 0; kc < 3; kc++){   // 64 k-rows per stage
            __syncthreads();   // prev chunk readers of bh done (iter0: LN order)
#pragma unroll
            for (int i = 0; i < 4; i++)
                *(uint4*)(bh + prow[i]*AHL + pc8[i]*8) = pf[i];
            ci++;
            if (ci < 9){
                int m2 = ci / 3, st = ci - m2*3;
                const __half* base = g_qkvh + (size_t)(st*64)*(3*DIMC) + m2*DIMC;
#pragma unroll
                for (int i = 0; i < 4; i++)
                    pf[i] = *(const uint4*)(base + (size_t)prow[i]*(3*DIMC) + pc8[i]*8);
            } else if (ci < 12){
                int st = ci - 9;
                const __half* base = g_projh + (size_t)(st*64)*DIMC;
#pragma unroll
                for (int i = 0; i < 4; i++)
                    pf[i] = *(const uint4*)(base + (size_t)prow[i]*DIMC + pc8[i]*8);
            }
            __syncthreads();
#pragma unroll
            for (int ks = 0; ks < 4; ks++){
                FA fa0, fa1;
                wmma::load_matrix_sync(fa0, xh + (rt0  )*16*AHL + kc*64 + ks*16, AHL);
                wmma::load_matrix_sync(fa1, xh + (rt0+1)*16*AHL + kc*64 + ks*16, AHL);
                FB fb0, fb1;
                wmma::load_matrix_sync(fb0, bh + ks*16*AHL + cgi*16, AHL);
                wmma::load_matrix_sync(fb1, bh + ks*16*AHL + (cgi+6)*16, AHL);
                wmma::mma_sync(acc[0][0], fa0, fb0, acc[0][0]);
                wmma::mma_sync(acc[0][1], fa0, fb1, acc[0][1]);
                wmma::mma_sync(acc[1][0], fa1, fb0, acc[1][0]);
                wmma::mma_sync(acc[1][1], fa1, fb1, acc[1][1]);
            }
        }
        // warp-local epilogue: store own tiles -> FS, bias + half-cvt -> dst.
        // (pad-row bias writes are harmless: S pad cols never read, Sh pads stay 0)
        {
            __half* dst = (m == 0) ? qh : (m == 1) ? kh : vh;
            const float* bb = qkv_b + m*DIMC;
#pragma unroll
            for (int i = 0; i < 2; i++){
                wmma::store_matrix_sync(FS + (rt0+i)*16*FLD + cgi*16,     acc[i][0], FLD, wmma::mem_row_major);
                wmma::store_matrix_sync(FS + (rt0+i)*16*FLD + (cgi+6)*16, acc[i][1], FLD, wmma::mem_row_major);
            }
            __syncwarp();
#pragma unroll
            for (int i = 0; i < 2; i++)
#pragma unroll
                for (int j = 0; j < 2; j++){
                    int r0 = (rt0+i)*16;
                    int c0 = ((j == 0) ? cgi : (cgi+6))*16;
#pragma unroll
                    for (int e = lane; e < 256; e += 32){
                        int rr = e >> 4, cc = e & 15;
                        dst[(r0+rr)*AHL + c0+cc] =
                            __float2half_rn(FS[(r0+rr)*FLD + c0+cc] + bb[c0+cc]);
                    }
                }
        }
        // next kc-loop-top / post-loop sync orders dst writes CTA-wide
    }
    __syncthreads();

    // ---- head groups of 3 ----
    for (int g = 0; g < 2; g++){
        // S = scale * Q K^T : 48 tiles, 4 per warp; f32 accum -> FS[64][192]
#pragma unroll
        for (int i = 0; i < 4; i++){
            int tt = wid + 12*i;
            int hh = tt >> 4, rem = tt & 15;
            int ti = rem >> 2, tj = rem & 3;
            int h = 3*g + hh;
            FC sacc; wmma::fill_fragment(sacc, 0.f);
#pragma unroll
            for (int ks = 0; ks < 2; ks++){
                FA fa;  wmma::load_matrix_sync(fa, qh + h*HD + ti*16*AHL + ks*16, AHL);
                FBt fb; wmma::load_matrix_sync(fb, kh + h*HD + tj*16*AHL + ks*16, AHL);
                wmma::mma_sync(sacc, fa, fb, sacc);
            }
#pragma unroll
            for (int e = 0; e < sacc.num_elements; e++)
                sacc.x[e] *= 0.17677669529663688110f;
            wmma::store_matrix_sync(FS + ti*16*FLD + hh*64 + tj*16, sacc, FLD,
                                    wmma::mem_row_major);
        }
        __syncthreads();

        // softmax: FS float -> Sh half (rows<49, cols<49; pads stay 0)
        for (int rr = wid; rr < 3*NTOKW; rr += 12){
            int hh = rr / NTOKW, r = rr - hh*NTOKW;
            const float* row = FS + r*FLD + hh*64;
            __half* orow = Sh + hh*64*SHL + r*SHL;
            float v0 = (lane      < NTOKW) ? row[lane     ] : -1e30f;
            float v1 = (lane + 32 < NTOKW) ? row[lane + 32] : -1e30f;
            float m  = warp_max(fmaxf(v0, v1));
            float e0 = (lane      < NTOKW) ? __expf(v0 - m) : 0.f;
            float e1 = (lane + 32 < NTOKW) ? __expf(v1 - m) : 0.f;
            float inv = 1.0f / warp_sum(e0 + e1);
            if (lane      < NTOKW) orow[lane     ] = __float2half_rn(e0 * inv);
            if (lane + 32 < NTOKW) orow[lane + 32] = __float2half_rn(e1 * inv);
        }
        __syncthreads();

        // PV: O_h[64,32] = P @ V_h; 24 tiles, 2 per warp; warp-local cvt -> xh
#pragma unroll
        for (int i = 0; i < 2; i++){
            int tt = wid + 12*i;
            int hh = tt >> 3, rem = tt & 7;
            int ti = rem >> 1, tj = rem & 1;
            int h = 3*g + hh;
            FC oacc; wmma::fill_fragment(oacc, 0.f);
#pragma unroll
            for (int ks = 0; ks < 4; ks++){
                FA fa; wmma::load_matrix_sync(fa, Sh + hh*64*SHL + ti*16*SHL + ks*16, SHL);
                FB fb; wmma::load_matrix_sync(fb, vh + h*HD + ks*16*AHL + tj*16, AHL);
                wmma::mma_sync(oacc, fa, fb, oacc);
            }
            wmma::store_matrix_sync(FS + ti*16*FLD + hh*32 + tj*16, oacc, FLD,
                                    wmma::mem_row_major);
            __syncwarp();
            // cvt own tile to xh (O pad rows are exact 0 via zero P pad rows)
            {
                int r0 = ti*16, c0 = hh*32 + tj*16;
#pragma unroll
                for (int e = lane; e < 256; e += 32){
                    int rr = e >> 4, cc = e & 15;
                    xh[(r0+rr)*AHL + g*96 + c0+cc] =
                        __float2half_rn(FS[(r0+rr)*FLD + c0+cc]);
                }
            }
        }
        __syncthreads();   // xh + FS writes visible before next S-phase / proj
    }

    // ---- proj: A = xh (O half); 3 x 64-row stages ----
    {
        FC acc[2][2];
#pragma unroll
        for (int i = 0; i < 2; i++)
#pragma unroll
            for (int j = 0; j < 2; j++) wmma::fill_fragment(acc[i][j], 0.f);

        for (int kc = 0; kc < 3; kc++){
            __syncthreads();
#pragma unroll
            for (int i = 0; i < 4; i++)
                *(uint4*)(bh + prow[i]*AHL + pc8[i]*8) = pf[i];
            ci++;
            if (ci < 12){
                int st = ci - 9;
                const __half* base = g_projh + (size_t)(st*64)*DIMC;
#pragma unroll
                for (int i = 0; i < 4; i++)
                    pf[i] = *(const uint4*)(base + (size_t)prow[i]*DIMC + pc8[i]*8);
            }
            __syncthreads();
#pragma unroll
            for (int ks = 0; ks < 4; ks++){
                FA fa0, fa1;
                wmma::load_matrix_sync(fa0, xh + (rt0  )*16*AHL + kc*64 + ks*16, AHL);
                wmma::load_matrix_sync(fa1, xh + (rt0+1)*16*AHL + kc*64 + ks*16, AHL);
                FB fb0, fb1;
                wmma::load_matrix_sync(fb0, bh + ks*16*AHL + cgi*16, AHL);
                wmma::load_matrix_sync(fb1, bh + ks*16*AHL + (cgi+6)*16, AHL);
                wmma::mma_sync(acc[0][0], fa0, fb0, acc[0][0]);
                wmma::mma_sync(acc[0][1], fa0, fb1, acc[0][1]);
                wmma::mma_sync(acc[1][0], fa1, fb0, acc[1][0]);
                wmma::mma_sync(acc[1][1], fa1, fb1, acc[1][1]);
            }
        }
#pragma unroll
        for (int i = 0; i < 2; i++){
            wmma::store_matrix_sync(FS + (rt0+i)*16*FLD + cgi*16,     acc[i][0], FLD, wmma::mem_row_major);
            wmma::store_matrix_sync(FS + (rt0+i)*16*FLD + (cgi+6)*16, acc[i][1], FLD, wmma::mem_row_major);
        }
        __syncthreads();

        // scatter (roll +3,+3) + proj bias
        float* ob = g_xattn + (size_t)b * NTOK * DIMC;
        for (int idx = t; idx < NTOKW*48; idx += AT_THREADS){
            int row = idx / 48, c4 = idx - row*48;
            int ti2 = row / WSZ, tj2 = row - ti2*WSZ;
            int sr = wr*WSZ + ti2 + SHIFT; if (sr >= HW) sr -= HW;
            int sc = wc*WSZ + tj2 + SHIFT; if (sc >= HW) sc -= HW;
            float4 v  = *(float4*)(FS + row*FLD + c4*4);
            float4 pb = *(const float4*)(proj_b + c4*4);
            v.x += pb.x; v.y += pb.y; v.z += pb.z; v.w += pb.w;
            *(float4*)(ob + (size_t)(sr*HW + sc)*DIMC + c4*4) = v;
        }
    }
}

// =====================================================================
// Kernel 2: fused MLP, fp16 wmma, 2 CTAs/SM, TM=64/256 threads, TH=64.
// w1 register-prefetched (no exposed wait); w2 via cp.async hidden
// behind GEMM1 + GELU.
// =====================================================================
#define ML_THREADS 256
#define TM 64
#define TH 64
#define XHL  200   // half stride, LN'd x
#define W1L  72    // half stride, w1 chunk [192][64]
#define HFL  68    // float stride, H accum scratch [64][64]
#define HHL  72    // half stride, gelu'd H [64][64]
#define W2L  200   // half stride, w2 chunk [64][192]
#define MO_XNH 0                      // half [64][200]  = 6400 floats
#define MO_W1H 6400                   // half [192][72]  = 6912 floats
#define MO_HF  13312                  // float [64][68]  = 4352
#define MO_HH  17664                  // half [64][72]   = 2304
#define MO_W2H 19968                  // half [64][200]  = 6400
#define MO_EPI 6400                   // float [64][196] (overlays W1H..W2H)
#define MLP_SMEM_FLOATS 26368
#define MLP_SMEM_BYTES  (MLP_SMEM_FLOATS*4)   // 105472 -> 2 CTAs/SM

__global__ __launch_bounds__(ML_THREADS, 2)
void mlp_kernel(const float* __restrict__ g2, const float* __restrict__ be2,
                const float* __restrict__ b1, const float* __restrict__ b2,
                float* __restrict__ out)
{
    extern __shared__ float sm[];
    __half* xnh = (__half*)(sm + MO_XNH);
    __half* w1h = (__half*)(sm + MO_W1H);
    float*  hf  = sm + MO_HF;
    __half* hhb = (__half*)(sm + MO_HH);
    __half* w2h = (__half*)(sm + MO_W2H);
    float*  epi = sm + MO_EPI;

    const int t = threadIdx.x;
    const int wid = t >> 5, lane = t & 31;
    const size_t tok0 = (size_t)blockIdx.x * TM;
    const float* xb = g_xattn + tok0 * DIMC;

    // w1 prefetch coords: [192][64] halfs = 1536 uint4, 6/thread
    int w1row[6], w1c8[6];
#pragma unroll
    for (int i = 0; i < 6; i++){
        int id = t + i*ML_THREADS;
        w1row[i] = id >> 3; w1c8[i] = id & 7;
    }
    uint4 w1pf[6];
#pragma unroll
    for (int i = 0; i < 6; i++)   // chunk 0
        w1pf[i] = *(const uint4*)(g_w1h + (size_t)w1row[i]*HIDDEN + w1c8[i]*8);

    // load x into epi, LN -> half xnh
    for (int idx = t; idx < TM*48; idx += ML_THREADS){
        int r = idx / 48, c4 = idx - r*48;
        *(float4*)(epi + r*FLD + c4*4) = *(const float4*)(xb + (size_t)r*DIMC + c4*4);
    }
    __syncthreads();
    for (int r = wid; r < TM; r += 8){
        float s = 0.f, s2 = 0.f;
#pragma unroll
        for (int c = lane; c < DIMC; c += 32){
            float v = epi[r*FLD + c]; s += v; s2 += v*v;
        }
        s = warp_sum(s); s2 = warp_sum(s2);
        float mu = s * (1.0f/DIMC);
        float rs = rsqrtf(s2*(1.0f/DIMC) - mu*mu + 1e-5f);
#pragma unroll
        for (int c = lane; c < DIMC; c += 32){
            float v = (epi[r*FLD + c] - mu)*rs*g2[c] + be2[c];
            xnh[r*XHL + c] = __float2half_rn(v);
        }
    }

    const int r1 = wid & 3, c10 = (wid >> 2) * 2;  // GEMM1: 2 col tiles/warp
    const int rp = wid & 1, cp = wid >> 1;         // GEMM2: 2x3 tiles/warp

    FC acc2[2][3];
#pragma unroll
    for (int i = 0; i < 2; i++)
#pragma unroll
        for (int j = 0; j < 3; j++) wmma::fill_fragment(acc2[i][j], 0.f);

    for (int hc = 0; hc < 12; hc++){
        const int h0 = hc * TH;
        __syncthreads();   // prev chunk readers done (iter0: LN reads of epi done)

        // STS prefetched w1 (no wait needed)
#pragma unroll
        for (int i = 0; i < 6; i++)
            *(uint4*)(w1h + w1row[i]*W1L + w1c8[i]*8) = w1pf[i];

        // stage w2 [64][192] halfs via cp.async (hidden behind GEMM1+GELU)
#pragma unroll
        for (int i = 0; i < 6; i++){
            int id = t + i*ML_THREADS;
            int row = id / 24, c8 = id - row*24;
            cp_async16(w2h + row*W2L + c8*8, g_w2h + (size_t)(h0 + row)*DIMC + c8*8);
        }
        cp_commit();

        // prefetch next chunk's w1 into regs (overlaps GEMM1/GELU/GEMM2)
        if (hc + 1 < 12){
            const __half* base = g_w1h + (size_t)(hc+1)*TH;
#pragma unroll
            for (int i = 0; i < 6; i++)
                w1pf[i] = *(const uint4*)(base + (size_t)w1row[i]*HIDDEN + w1c8[i]*8);
        }
        __syncthreads();   // w1h visible CTA-wide

        // GEMM1: H[64,64] = Xn[64,192] @ W1c[192,64]; 2 tiles/warp, fa reuse
        FC a1[2];
        wmma::fill_fragment(a1[0], 0.f);
        wmma::fill_fragment(a1[1], 0.f);
#pragma unroll
        for (int ks = 0; ks < 12; ks++){
            FA fa; wmma::load_matrix_sync(fa, xnh + r1*16*XHL + ks*16, XHL);
            FB fb0, fb1;
            wmma::load_matrix_sync(fb0, w1h + ks*16*W1L + (c10  )*16, W1L);
            wmma::load_matrix_sync(fb1, w1h + ks*16*W1L + (c10+1)*16, W1L);
            wmma::mma_sync(a1[0], fa, fb0, a1[0]);
            wmma::mma_sync(a1[1], fa, fb1, a1[1]);
        }
#pragma unroll
        for (int j = 0; j < 2; j++)
            wmma::store_matrix_sync(hf + r1*16*HFL + (c10+j)*16, a1[j], HFL,
                                    wmma::mem_row_major);
        __syncwarp();
        {   // bias + exact GELU on own 2 tiles -> half
#pragma unroll
            for (int j = 0; j < 2; j++){
                float*  tf = hf  + r1*16*HFL + (c10+j)*16;
                __half* th = hhb + r1*16*HHL + (c10+j)*16;
                const float* bp = b1 + h0 + (c10+j)*16;
#pragma unroll
                for (int e = lane; e < 256; e += 32){
                    int rr = e >> 4, cc = e & 15;
                    th[rr*HHL + cc] = __float2half_rn(gelu_exact(tf[rr*HFL + cc] + bp[cc]));
                }
            }
        }
        cp_wait<0>();      // w2 arrived (hidden behind GEMM1 + GELU)
        __syncthreads();

        // GEMM2: acc2 += H[64,64] @ W2c[64,192]; K=64 -> 4 k-steps
#pragma unroll
        for (int ks = 0; ks < 4; ks++){
            FA fa0, fa1;
            wmma::load_matrix_sync(fa0, hhb + (2*rp  )*16*HHL + ks*16, HHL);
            wmma::load_matrix_sync(fa1, hhb + (2*rp+1)*16*HHL + ks*16, HHL);
#pragma unroll
            for (int j = 0; j < 3; j++){
                FB fb; wmma::load_matrix_sync(fb, w2h + ks*16*W2L + (3*cp + j)*16, W2L);
                wmma::mma_sync(acc2[0][j], fa0, fb, acc2[0][j]);
                wmma::mma_sync(acc2[1][j], fa1, fb, acc2[1][j]);
            }
        }
    }
    __syncthreads();

    // epilogue: acc2 -> epi (overlays weight buffers, all dead)
#pragma unroll
    for (int i = 0; i < 2; i++)
#pragma unroll
        for (int j = 0; j < 3; j++)
            wmma::store_matrix_sync(epi + (2*rp+i)*16*FLD + (3*cp+j)*16, acc2[i][j],
                                    FLD, wmma::mem_row_major);
    __syncthreads();

    float* ob = out + tok0 * DIMC;
    for (int idx = t; idx < TM*48; idx += ML_THREADS){
        int r = idx / 48, c4 = idx - r*48;
        float4 a  = *(float4*)(epi + r*FLD + c4*4);
        float4 xr = *(const float4*)(xb + (size_t)r*DIMC + c4*4);
        float4 bb = *(const float4*)(b2 + c4*4);
        a.x += xr.x + bb.x; a.y += xr.y + bb.y;
        a.z += xr.z + bb.z; a.w += xr.w + bb.w;
        *(float4*)(ob + (size_t)r*DIMC + c4*4) = a;
    }
}

// =====================================================================
// launch
// =====================================================================
extern "C" void kernel_launch(void* const* d_in, const int* in_sizes, int n_in,
                              void* d_out, int out_size)
{
    (void)in_sizes; (void)n_in; (void)out_size;
    const float* x      = (const float*)d_in[0];
    const float* qkv_w  = (const float*)d_in[1];
    const float* qkv_b  = (const float*)d_in[2];
    const float* proj_w = (const float*)d_in[3];
    const float* proj_b = (const float*)d_in[4];
    const float* g1     = (const float*)d_in[5];
    const float* be1    = (const float*)d_in[6];
    const float* g2     = (const float*)d_in[7];
    const float* be2    = (const float*)d_in[8];
    const float* w1     = (const float*)d_in[9];
    const float* b1     = (const float*)d_in[10];
    const float* w2     = (const float*)d_in[11];
    const float* b2     = (const float*)d_in[12];
    float* out = (float*)d_out;

    cudaFuncSetAttribute(attn_kernel, cudaFuncAttributeMaxDynamicSharedMemorySize, ATT_SMEM_BYTES);
    cudaFuncSetAttribute(mlp_kernel,  cudaFuncAttributeMaxDynamicSharedMemorySize, MLP_SMEM_BYTES);

    prep_kernel<<<RW_BLOCKS, RW_THREADS>>>(w1, w2, qkv_w, proj_w);
    attn_kernel<<<NBLKS, AT_THREADS, ATT_SMEM_BYTES>>>(x, qkv_b, proj_b, g1, be1);
    mlp_kernel<<<(BATCH*NTOK)/TM, ML_THREADS, MLP_SMEM_BYTES>>>(g2, be2, b1, b2, out);
}